// round 6
// baseline (speedup 1.0000x reference)
#include <cuda_runtime.h>
#include <math.h>

#define BATCH 2
#define NTOK  2048
#define CDIM  768
#define HEADS 12
#define DHEAD 64
#define HALF  64
#define SCALE 0.125f  /* 64^-0.5 */

// ---------------- scratch (device globals; no allocations allowed) ----------
__device__ float g_Q[(size_t)BATCH * HEADS * NTOK * DHEAD];
__device__ float g_K[(size_t)BATCH * HEADS * NTOK * DHEAD];
__device__ float g_V[(size_t)BATCH * HEADS * NTOK * DHEAD];
__device__ float g_O[(size_t)BATCH * NTOK * CDIM];

// ---------------- SGEMM: C[M,Nc] = A[M,768] @ B[Nc,768]^T ------------------
// MODE 0: A = x, scatter columns into g_Q/g_K/g_V per-head layout.
// MODE 1: A = g_O (param ignored), C = out + bias (broadcast over rows).
// Block tile 128x128, K-tile 8, 256 threads, 8x8 per-thread micro-tile.
template <int MODE>
__global__ void __launch_bounds__(256) sgemm768(const float* __restrict__ A,
                                                const float* __restrict__ Bw,
                                                const float* __restrict__ bias,
                                                float* __restrict__ Cout) {
    constexpr int K = CDIM;
    __shared__ float As[8][128];
    __shared__ float Bs[8][128];

    const int tid = threadIdx.x;
    const int rowBase = blockIdx.y * 128;
    const int colBase = blockIdx.x * 128;
    const int loadRow = tid >> 1;          // 0..127
    const int loadCol = (tid & 1) << 2;    // 0 or 4
    const int tr = tid >> 4;               // 0..15
    const int tc = tid & 15;               // 0..15

    const float* Ablk = ((MODE == 1) ? (const float*)g_O : A) + (size_t)rowBase * K;
    const float* Bblk = Bw + (size_t)colBase * K;

    float acc[8][8] = {};

    for (int k0 = 0; k0 < K; k0 += 8) {
        float4 av = *reinterpret_cast<const float4*>(Ablk + (size_t)loadRow * K + k0 + loadCol);
        float4 bv = *reinterpret_cast<const float4*>(Bblk + (size_t)loadRow * K + k0 + loadCol);
        As[loadCol + 0][loadRow] = av.x;
        As[loadCol + 1][loadRow] = av.y;
        As[loadCol + 2][loadRow] = av.z;
        As[loadCol + 3][loadRow] = av.w;
        Bs[loadCol + 0][loadRow] = bv.x;
        Bs[loadCol + 1][loadRow] = bv.y;
        Bs[loadCol + 2][loadRow] = bv.z;
        Bs[loadCol + 3][loadRow] = bv.w;
        __syncthreads();

#pragma unroll
        for (int kk = 0; kk < 8; kk++) {
            float4 a0 = *reinterpret_cast<const float4*>(&As[kk][tr * 8]);
            float4 a1 = *reinterpret_cast<const float4*>(&As[kk][tr * 8 + 4]);
            float4 b0 = *reinterpret_cast<const float4*>(&Bs[kk][tc * 8]);
            float4 b1 = *reinterpret_cast<const float4*>(&Bs[kk][tc * 8 + 4]);
            float am[8] = {a0.x, a0.y, a0.z, a0.w, a1.x, a1.y, a1.z, a1.w};
            float bn[8] = {b0.x, b0.y, b0.z, b0.w, b1.x, b1.y, b1.z, b1.w};
#pragma unroll
            for (int i = 0; i < 8; i++)
#pragma unroll
                for (int j = 0; j < 8; j++)
                    acc[i][j] = fmaf(am[i], bn[j], acc[i][j]);
        }
        __syncthreads();
    }

    if (MODE == 0) {
        // Scatter into Q/K/V: column e = t*768 + h*64 + d (t in {q,k,v})
#pragma unroll
        for (int i = 0; i < 8; i++) {
            int m = rowBase + tr * 8 + i;
            int b = m >> 11;           // /2048
            int n = m & (NTOK - 1);
#pragma unroll
            for (int jj = 0; jj < 8; jj += 4) {
                int e = colBase + tc * 8 + jj;
                int t = e / CDIM;
                int r = e - t * CDIM;
                int h = r >> 6;
                int d = r & 63;
                float* dst = (t == 0) ? g_Q : ((t == 1) ? g_K : g_V);
                float4 v = make_float4(acc[i][jj], acc[i][jj + 1], acc[i][jj + 2], acc[i][jj + 3]);
                *reinterpret_cast<float4*>(
                    &dst[(((size_t)(b * HEADS + h)) * NTOK + n) * DHEAD + d]) = v;
            }
        }
    } else {
#pragma unroll
        for (int i = 0; i < 8; i++) {
            int m = rowBase + tr * 8 + i;
#pragma unroll
            for (int jj = 0; jj < 8; jj += 4) {
                int col = colBase + tc * 8 + jj;
                float4 bb = *reinterpret_cast<const float4*>(&bias[col]);
                float4 v = make_float4(acc[i][jj] + bb.x, acc[i][jj + 1] + bb.y,
                                       acc[i][jj + 2] + bb.z, acc[i][jj + 3] + bb.w);
                *reinterpret_cast<float4*>(&Cout[(size_t)m * CDIM + col]) = v;
            }
        }
    }
}

// ---------------- Sliding-window attention ---------------------------------
// One CTA per (b*H+h, 64-query tile). Keys needed: [q0-64, q0+127] -> 192 slots.
#define KSLOTS 192
#define SQ_STRIDE 68
#define SK_STRIDE 196
#define SV_STRIDE 68
constexpr int SQ_OFF = 0;
constexpr int SK_OFF = 64 * SQ_STRIDE;              // 4352
constexpr int SV_OFF = SK_OFF + 64 * SK_STRIDE;     // 16896
constexpr int SMEM_FLOATS = SV_OFF + KSLOTS * SV_STRIDE;  // 29952 -> 119808 B

__global__ void __launch_bounds__(256) attn_kernel() {
    extern __shared__ float sm[];
    float* sQ = sm + SQ_OFF;   // [d][q]  d-major, stride 68
    float* sK = sm + SK_OFF;   // [d][s]  stride 196
    float* sV = sm + SV_OFF;   // [s][d]  stride 68
    float* sS = sK;            // S overlays K (same 64x196 footprint)

    const int tid = threadIdx.x;
    const int q0 = blockIdx.x * 64;
    const int bh = blockIdx.y;
    const int kstart = q0 - HALF;

    const float* Qg = g_Q + (size_t)bh * NTOK * DHEAD;
    const float* Kg = g_K + (size_t)bh * NTOK * DHEAD;
    const float* Vg = g_V + (size_t)bh * NTOK * DHEAD;

    // Load Q transposed into smem
    for (int idx = tid; idx < 64 * 16; idx += 256) {
        int q = idx >> 4, d4 = (idx & 15) << 2;
        float4 v = *reinterpret_cast<const float4*>(&Qg[(size_t)(q0 + q) * DHEAD + d4]);
        sQ[(d4 + 0) * SQ_STRIDE + q] = v.x;
        sQ[(d4 + 1) * SQ_STRIDE + q] = v.y;
        sQ[(d4 + 2) * SQ_STRIDE + q] = v.z;
        sQ[(d4 + 3) * SQ_STRIDE + q] = v.w;
    }
    // Load K (transposed) and V (row-major), zero-padded out of range
    for (int idx = tid; idx < KSLOTS * 16; idx += 256) {
        int s = idx >> 4, d4 = (idx & 15) << 2;
        int j = kstart + s;
        float4 kv = make_float4(0.f, 0.f, 0.f, 0.f);
        float4 vv = kv;
        if (j >= 0 && j < NTOK) {
            kv = *reinterpret_cast<const float4*>(&Kg[(size_t)j * DHEAD + d4]);
            vv = *reinterpret_cast<const float4*>(&Vg[(size_t)j * DHEAD + d4]);
        }
        sK[(d4 + 0) * SK_STRIDE + s] = kv.x;
        sK[(d4 + 1) * SK_STRIDE + s] = kv.y;
        sK[(d4 + 2) * SK_STRIDE + s] = kv.z;
        sK[(d4 + 3) * SK_STRIDE + s] = kv.w;
        *reinterpret_cast<float4*>(&sV[s * SV_STRIDE + d4]) = vv;
    }
    __syncthreads();

    const int tr = tid >> 4, tc = tid & 15;
    const int qr = tr * 4, kc = tc * 12;

    // GEMM1: S[64,192] = Q K^T  (4x12 per thread)
    float acc[4][12] = {};
#pragma unroll 8
    for (int d = 0; d < DHEAD; d++) {
        float4 a = *reinterpret_cast<const float4*>(&sQ[d * SQ_STRIDE + qr]);
        float am[4] = {a.x, a.y, a.z, a.w};
        float bn[12];
#pragma unroll
        for (int h2 = 0; h2 < 3; h2++) {
            float4 b = *reinterpret_cast<const float4*>(&sK[d * SK_STRIDE + kc + 4 * h2]);
            bn[4 * h2 + 0] = b.x; bn[4 * h2 + 1] = b.y;
            bn[4 * h2 + 2] = b.z; bn[4 * h2 + 3] = b.w;
        }
#pragma unroll
        for (int i = 0; i < 4; i++)
#pragma unroll
            for (int j = 0; j < 12; j++)
                acc[i][j] = fmaf(am[i], bn[j], acc[i][j]);
    }
    __syncthreads();  // done reading sK; its space becomes sS

    // Scale + mask, write S
#pragma unroll
    for (int i = 0; i < 4; i++) {
        int qi = qr + i;
#pragma unroll
        for (int j = 0; j < 12; j++) {
            int s = kc + j;
            int kj = kstart + s;
            int diff = qi + HALF - s;  // = q_global - key_global
            bool ok = (kj >= 0) & (kj < NTOK) & (diff >= -HALF) & (diff <= HALF);
            sS[qi * SK_STRIDE + s] = ok ? acc[i][j] * SCALE : -3.0e38f;
        }
    }
    __syncthreads();

    // Softmax: one thread per query row (each row always has >=1 valid key)
    if (tid < 64) {
        float* row = &sS[tid * SK_STRIDE];
        float mx = -3.0e38f;
        for (int s = 0; s < KSLOTS; s++) mx = fmaxf(mx, row[s]);
        float sum = 0.f;
        for (int s = 0; s < KSLOTS; s++) {
            float e = __expf(row[s] - mx);
            row[s] = e;
            sum += e;
        }
        float inv = __fdividef(1.f, sum);
        for (int s = 0; s < KSLOTS; s++) row[s] *= inv;
    }
    __syncthreads();

    // GEMM2: O[64,64] = P @ V  (4x4 per thread)
    float o[4][4] = {};
    const int dc = tc * 4;
#pragma unroll 4
    for (int s = 0; s < KSLOTS; s++) {
        float p[4];
#pragma unroll
        for (int i = 0; i < 4; i++) p[i] = sS[(qr + i) * SK_STRIDE + s];
        float4 vq = *reinterpret_cast<const float4*>(&sV[s * SV_STRIDE + dc]);
        float vn[4] = {vq.x, vq.y, vq.z, vq.w};
#pragma unroll
        for (int i = 0; i < 4; i++)
#pragma unroll
            for (int j = 0; j < 4; j++)
                o[i][j] = fmaf(p[i], vn[j], o[i][j]);
    }

    const int b = bh / HEADS, h = bh - b * HEADS;
#pragma unroll
    for (int i = 0; i < 4; i++) {
        int n = q0 + qr + i;
        *reinterpret_cast<float4*>(&g_O[((size_t)b * NTOK + n) * CDIM + h * DHEAD + dc]) =
            make_float4(o[i][0], o[i][1], o[i][2], o[i][3]);
    }
}

// ---------------- launch ----------------------------------------------------
extern "C" void kernel_launch(void* const* d_in, const int* in_sizes, int n_in,
                              void* d_out, int out_size) {
    (void)in_sizes; (void)n_in; (void)out_size;
    const float* x      = (const float*)d_in[0];
    const float* w_qkv  = (const float*)d_in[1];
    const float* w_proj = (const float*)d_in[2];
    const float* b_proj = (const float*)d_in[3];
    float* out = (float*)d_out;

    // 119,808 B dynamic smem > 48 KB default; attribute set is idempotent.
    cudaFuncSetAttribute(attn_kernel, cudaFuncAttributeMaxDynamicSharedMemorySize,
                         SMEM_FLOATS * (int)sizeof(float));

    // 1) QKV projection -> Q/K/V buffers
    sgemm768<0><<<dim3(3 * CDIM / 128, BATCH * NTOK / 128), 256>>>(x, w_qkv, nullptr, nullptr);

    // 2) Sliding-window attention -> g_O ([B,N,C] layout)
    attn_kernel<<<dim3(NTOK / 64, BATCH * HEADS), 256,
                  SMEM_FLOATS * (int)sizeof(float)>>>();

    // 3) Output projection + bias -> d_out
    sgemm768<1><<<dim3(CDIM / 128, BATCH * NTOK / 128), 256>>>(nullptr, w_proj, b_proj, out);
}

// round 8
// speedup vs baseline: 2.1595x; 2.1595x over previous
#include <cuda_runtime.h>
#include <cuda_bf16.h>
#include <stdint.h>
#include <math.h>

#define BATCH 2
#define NTOK  2048
#define CDIM  768
#define HEADS 12
#define DHEAD 64
#define HALF  64
#define SCALE 0.125f  /* 64^-0.5 */

// ---------------- scratch (device globals; no allocations allowed) ----------
__device__ float g_Q[(size_t)BATCH * HEADS * NTOK * DHEAD];
__device__ float g_K[(size_t)BATCH * HEADS * NTOK * DHEAD];
__device__ float g_V[(size_t)BATCH * HEADS * NTOK * DHEAD];
__device__ float g_O[(size_t)BATCH * NTOK * CDIM];

// ---------------- helpers ----------------------------------------------------
__device__ __forceinline__ uint32_t smem_u32(const void* p) {
    uint32_t a;
    asm("{ .reg .u64 t; cvta.to.shared.u64 t, %1; cvt.u32.u64 %0, t; }"
        : "=r"(a) : "l"(p));
    return a;
}
__device__ __forceinline__ void ldsm4(uint32_t* r, uint32_t addr) {
    asm volatile("ldmatrix.sync.aligned.m8n8.x4.shared.b16 {%0,%1,%2,%3}, [%4];"
                 : "=r"(r[0]), "=r"(r[1]), "=r"(r[2]), "=r"(r[3]) : "r"(addr));
}
__device__ __forceinline__ void mma16816(float* d, const uint32_t* a,
                                         const uint32_t* b) {
    asm volatile(
        "mma.sync.aligned.m16n8k16.row.col.f32.bf16.bf16.f32 "
        "{%0,%1,%2,%3}, {%4,%5,%6,%7}, {%8,%9}, {%0,%1,%2,%3};"
        : "+f"(d[0]), "+f"(d[1]), "+f"(d[2]), "+f"(d[3])
        : "r"(a[0]), "r"(a[1]), "r"(a[2]), "r"(a[3]), "r"(b[0]), "r"(b[1]));
}
__device__ __forceinline__ uint32_t bits2(__nv_bfloat162 v) {
    return *reinterpret_cast<uint32_t*>(&v);
}

// ---------------- bf16x3 mma.sync GEMM: C[M,Nc] = A[M,768] @ B[Nc,768]^T -----
// MODE 0: A = x, scatter 2304 cols into g_Q/g_K/g_V per-head layout.
// MODE 1: A = g_O, C = d_out + bias.
// CTA 128x128, K-chunk 32, 256 threads (8 warps as 2x4, warp tile 64x32).
// smem per buffer: AHI | ALO | BHI | BLO, each [128][40] bf16 (80B padded rows).
#define BK 32
#define SSTR 40
#define ATILE_B (128 * SSTR * 2)   /* 10240 */
#define BUF_B   (4 * ATILE_B)      /* 40960 */
#define GSMEM_BYTES (2 * BUF_B)    /* 81920 */
#define NCHUNK (CDIM / BK)         /* 24 */

template <int MODE>
__global__ void __launch_bounds__(256, 1) tcgemm(const float* __restrict__ A,
                                                 const float* __restrict__ Bw,
                                                 const float* __restrict__ bias,
                                                 float* __restrict__ Cout) {
    extern __shared__ __align__(128) char smem[];
    const int tid = threadIdx.x;
    const int wid = tid >> 5, lane = tid & 31;
    const int m0w = (wid >> 2) * 64;   // warp M offset in tile
    const int n0w = (wid & 3) * 32;    // warp N offset in tile
    const int rowBase = blockIdx.y * 128;
    const int colBase = blockIdx.x * 128;
    const float* Asrc = (MODE == 1) ? (const float*)g_O : A;
    const uint32_t sbase = smem_u32(smem);

    const int sr = tid >> 3;        // staging row base (0..31), rows sr+32u
    const int sc = (tid & 7) * 4;   // staging col (floats)

    float4 aR[4], bR[4];
    auto ldgch = [&](int k0) {
#pragma unroll
        for (int u = 0; u < 4; u++) {
            int r = u * 32 + sr;
            aR[u] = *reinterpret_cast<const float4*>(
                Asrc + (size_t)(rowBase + r) * CDIM + k0 + sc);
            bR[u] = *reinterpret_cast<const float4*>(
                Bw + (size_t)(colBase + r) * CDIM + k0 + sc);
        }
    };

    float acc[4][4][4] = {};
    ldgch(0);

    for (int c = 0; c < NCHUNK; c++) {
        char* bufp = smem + (c & 1) * BUF_B;
        const uint32_t bufu = sbase + (c & 1) * BUF_B;

        // stage + hi/lo split
#pragma unroll
        for (int u = 0; u < 4; u++) {
            int r = u * 32 + sr;
            uint32_t off = (uint32_t)(r * SSTR + sc) * 2;

            float4 v = aR[u];
            __nv_bfloat162 h01 = __floats2bfloat162_rn(v.x, v.y);
            __nv_bfloat162 h23 = __floats2bfloat162_rn(v.z, v.w);
            __nv_bfloat162 l01 = __floats2bfloat162_rn(v.x - __low2float(h01),
                                                       v.y - __high2float(h01));
            __nv_bfloat162 l23 = __floats2bfloat162_rn(v.z - __low2float(h23),
                                                       v.w - __high2float(h23));
            *reinterpret_cast<uint2*>(bufp + off) = make_uint2(bits2(h01), bits2(h23));
            *reinterpret_cast<uint2*>(bufp + ATILE_B + off) =
                make_uint2(bits2(l01), bits2(l23));

            v = bR[u];
            h01 = __floats2bfloat162_rn(v.x, v.y);
            h23 = __floats2bfloat162_rn(v.z, v.w);
            l01 = __floats2bfloat162_rn(v.x - __low2float(h01),
                                        v.y - __high2float(h01));
            l23 = __floats2bfloat162_rn(v.z - __low2float(h23),
                                        v.w - __high2float(h23));
            *reinterpret_cast<uint2*>(bufp + 2 * ATILE_B + off) =
                make_uint2(bits2(h01), bits2(h23));
            *reinterpret_cast<uint2*>(bufp + 3 * ATILE_B + off) =
                make_uint2(bits2(l01), bits2(l23));
        }
        __syncthreads();

        if (c + 1 < NCHUNK) ldgch((c + 1) * BK);  // prefetch next chunk

#pragma unroll
        for (int ks = 0; ks < 2; ks++) {
            const int k16 = ks * 16;
            uint32_t aHi[4][4], aLo[4][4], bHi[2][4], bLo[2][4];

            // A frags: lane -> row m0w+16mi+(lane%16), col k16+(lane/16)*8
            uint32_t aoff =
                bufu + (uint32_t)((m0w + (lane & 15)) * SSTR + k16 + (lane >> 4) * 8) * 2;
#pragma unroll
            for (int mi = 0; mi < 4; mi++) {
                ldsm4(aHi[mi], aoff + mi * (16 * SSTR * 2));
                ldsm4(aLo[mi], aoff + ATILE_B + mi * (16 * SSTR * 2));
            }
            // B frags: x4 covers two 8-col n-tiles
            {
                int g = lane >> 3, w8 = lane & 7;
                int brow = n0w + (g >> 1) * 8 + w8;
                uint32_t boff = bufu + 2 * ATILE_B +
                                (uint32_t)(brow * SSTR + k16 + (g & 1) * 8) * 2;
#pragma unroll
                for (int np = 0; np < 2; np++) {
                    ldsm4(bHi[np], boff + np * (16 * SSTR * 2));
                    ldsm4(bLo[np], boff + ATILE_B + np * (16 * SSTR * 2));
                }
            }
#pragma unroll
            for (int mi = 0; mi < 4; mi++)
#pragma unroll
                for (int ni = 0; ni < 4; ni++) {
                    const uint32_t* bh = &bHi[ni >> 1][(ni & 1) * 2];
                    const uint32_t* bl = &bLo[ni >> 1][(ni & 1) * 2];
                    mma16816(acc[mi][ni], aHi[mi], bh);
                    mma16816(acc[mi][ni], aHi[mi], bl);
                    mma16816(acc[mi][ni], aLo[mi], bh);
                }
        }
    }

    // Epilogue straight from registers.
    // d0,d1 -> row (lane>>2), cols 2*(lane&3)+{0,1}; d2,d3 -> row+8.
#pragma unroll
    for (int mi = 0; mi < 4; mi++) {
        int m = rowBase + m0w + 16 * mi + (lane >> 2);
#pragma unroll
        for (int ni = 0; ni < 4; ni++) {
            int e = colBase + n0w + 8 * ni + (lane & 3) * 2;
            float2 v0 = make_float2(acc[mi][ni][0], acc[mi][ni][1]);
            float2 v1 = make_float2(acc[mi][ni][2], acc[mi][ni][3]);
            if (MODE == 0) {
                int tsel = e / CDIM;
                int rr = e - tsel * CDIM;
                int h = rr >> 6, d = rr & 63;
                float* dst = (tsel == 0) ? g_Q : ((tsel == 1) ? g_K : g_V);
                int bb = m >> 11, n = m & (NTOK - 1);
                size_t base = ((size_t)(bb * HEADS + h)) * NTOK;
                *reinterpret_cast<float2*>(&dst[(base + n) * DHEAD + d]) = v0;
                *reinterpret_cast<float2*>(&dst[(base + n + 8) * DHEAD + d]) = v1;
            } else {
                float2 bv = *reinterpret_cast<const float2*>(&bias[e]);
                v0.x += bv.x; v0.y += bv.y;
                v1.x += bv.x; v1.y += bv.y;
                *reinterpret_cast<float2*>(&Cout[(size_t)m * CDIM + e]) = v0;
                *reinterpret_cast<float2*>(&Cout[(size_t)(m + 8) * CDIM + e]) = v1;
            }
        }
    }
}

// ---------------- Sliding-window attention (fp32, unchanged) ---------------
#define KSLOTS 192
#define SQ_STRIDE 68
#define SK_STRIDE 196
#define SV_STRIDE 68
constexpr int SQ_OFF = 0;
constexpr int SK_OFF = 64 * SQ_STRIDE;
constexpr int SV_OFF = SK_OFF + 64 * SK_STRIDE;
constexpr int SMEM_FLOATS = SV_OFF + KSLOTS * SV_STRIDE;

__global__ void __launch_bounds__(256) attn_kernel() {
    extern __shared__ float sm[];
    float* sQ = sm + SQ_OFF;
    float* sK = sm + SK_OFF;
    float* sV = sm + SV_OFF;
    float* sS = sK;

    const int tid = threadIdx.x;
    const int q0 = blockIdx.x * 64;
    const int bh = blockIdx.y;
    const int kstart = q0 - HALF;

    const float* Qg = g_Q + (size_t)bh * NTOK * DHEAD;
    const float* Kg = g_K + (size_t)bh * NTOK * DHEAD;
    const float* Vg = g_V + (size_t)bh * NTOK * DHEAD;

    for (int idx = tid; idx < 64 * 16; idx += 256) {
        int q = idx >> 4, d4 = (idx & 15) << 2;
        float4 v = *reinterpret_cast<const float4*>(&Qg[(size_t)(q0 + q) * DHEAD + d4]);
        sQ[(d4 + 0) * SQ_STRIDE + q] = v.x;
        sQ[(d4 + 1) * SQ_STRIDE + q] = v.y;
        sQ[(d4 + 2) * SQ_STRIDE + q] = v.z;
        sQ[(d4 + 3) * SQ_STRIDE + q] = v.w;
    }
    for (int idx = tid; idx < KSLOTS * 16; idx += 256) {
        int s = idx >> 4, d4 = (idx & 15) << 2;
        int j = kstart + s;
        float4 kv = make_float4(0.f, 0.f, 0.f, 0.f);
        float4 vv = kv;
        if (j >= 0 && j < NTOK) {
            kv = *reinterpret_cast<const float4*>(&Kg[(size_t)j * DHEAD + d4]);
            vv = *reinterpret_cast<const float4*>(&Vg[(size_t)j * DHEAD + d4]);
        }
        sK[(d4 + 0) * SK_STRIDE + s] = kv.x;
        sK[(d4 + 1) * SK_STRIDE + s] = kv.y;
        sK[(d4 + 2) * SK_STRIDE + s] = kv.z;
        sK[(d4 + 3) * SK_STRIDE + s] = kv.w;
        *reinterpret_cast<float4*>(&sV[s * SV_STRIDE + d4]) = vv;
    }
    __syncthreads();

    const int tr = tid >> 4, tc = tid & 15;
    const int qr = tr * 4, kc = tc * 12;

    float acc[4][12] = {};
#pragma unroll 8
    for (int d = 0; d < DHEAD; d++) {
        float4 a = *reinterpret_cast<const float4*>(&sQ[d * SQ_STRIDE + qr]);
        float am[4] = {a.x, a.y, a.z, a.w};
        float bn[12];
#pragma unroll
        for (int h2 = 0; h2 < 3; h2++) {
            float4 b = *reinterpret_cast<const float4*>(&sK[d * SK_STRIDE + kc + 4 * h2]);
            bn[4 * h2 + 0] = b.x; bn[4 * h2 + 1] = b.y;
            bn[4 * h2 + 2] = b.z; bn[4 * h2 + 3] = b.w;
        }
#pragma unroll
        for (int i = 0; i < 4; i++)
#pragma unroll
            for (int j = 0; j < 12; j++)
                acc[i][j] = fmaf(am[i], bn[j], acc[i][j]);
    }
    __syncthreads();

#pragma unroll
    for (int i = 0; i < 4; i++) {
        int qi = qr + i;
#pragma unroll
        for (int j = 0; j < 12; j++) {
            int s = kc + j;
            int kj = kstart + s;
            int diff = qi + HALF - s;
            bool ok = (kj >= 0) & (kj < NTOK) & (diff >= -HALF) & (diff <= HALF);
            sS[qi * SK_STRIDE + s] = ok ? acc[i][j] * SCALE : -3.0e38f;
        }
    }
    __syncthreads();

    if (tid < 64) {
        float* row = &sS[tid * SK_STRIDE];
        float mx = -3.0e38f;
        for (int s = 0; s < KSLOTS; s++) mx = fmaxf(mx, row[s]);
        float sum = 0.f;
        for (int s = 0; s < KSLOTS; s++) {
            float e = __expf(row[s] - mx);
            row[s] = e;
            sum += e;
        }
        float inv = __fdividef(1.f, sum);
        for (int s = 0; s < KSLOTS; s++) row[s] *= inv;
    }
    __syncthreads();

    float o[4][4] = {};
    const int dc = tc * 4;
#pragma unroll 4
    for (int s = 0; s < KSLOTS; s++) {
        float p[4];
#pragma unroll
        for (int i = 0; i < 4; i++) p[i] = sS[(qr + i) * SK_STRIDE + s];
        float4 vq = *reinterpret_cast<const float4*>(&sV[s * SV_STRIDE + dc]);
        float vn[4] = {vq.x, vq.y, vq.z, vq.w};
#pragma unroll
        for (int i = 0; i < 4; i++)
#pragma unroll
            for (int j = 0; j < 4; j++)
                o[i][j] = fmaf(p[i], vn[j], o[i][j]);
    }

    const int b = bh / HEADS, h = bh - b * HEADS;
#pragma unroll
    for (int i = 0; i < 4; i++) {
        int n = q0 + qr + i;
        *reinterpret_cast<float4*>(&g_O[((size_t)b * NTOK + n) * CDIM + h * DHEAD + dc]) =
            make_float4(o[i][0], o[i][1], o[i][2], o[i][3]);
    }
}

// ---------------- launch ----------------------------------------------------
extern "C" void kernel_launch(void* const* d_in, const int* in_sizes, int n_in,
                              void* d_out, int out_size) {
    (void)in_sizes; (void)n_in; (void)out_size;
    const float* x      = (const float*)d_in[0];
    const float* w_qkv  = (const float*)d_in[1];
    const float* w_proj = (const float*)d_in[2];
    const float* b_proj = (const float*)d_in[3];
    float* out = (float*)d_out;

    cudaFuncSetAttribute(tcgemm<0>, cudaFuncAttributeMaxDynamicSharedMemorySize,
                         GSMEM_BYTES);
    cudaFuncSetAttribute(tcgemm<1>, cudaFuncAttributeMaxDynamicSharedMemorySize,
                         GSMEM_BYTES);
    cudaFuncSetAttribute(attn_kernel, cudaFuncAttributeMaxDynamicSharedMemorySize,
                         SMEM_FLOATS * (int)sizeof(float));

    // 1) QKV projection (bf16x3 mma.sync) -> Q/K/V per-head buffers
    tcgemm<0><<<dim3(3 * CDIM / 128, BATCH * NTOK / 128), 256, GSMEM_BYTES>>>(
        x, w_qkv, nullptr, nullptr);

    // 2) Sliding-window attention -> g_O ([B,N,C] layout)
    attn_kernel<<<dim3(NTOK / 64, BATCH * HEADS), 256,
                  SMEM_FLOATS * (int)sizeof(float)>>>();

    // 3) Output projection + bias (bf16x3 mma.sync) -> d_out
    tcgemm<1><<<dim3(CDIM / 128, BATCH * NTOK / 128), 256, GSMEM_BYTES>>>(
        nullptr, w_proj, b_proj, out);
}

// round 9
// speedup vs baseline: 2.5219x; 1.1678x over previous
#include <cuda_runtime.h>
#include <cuda_bf16.h>
#include <stdint.h>
#include <math.h>

#define BATCH 2
#define NTOK  2048
#define CDIM  768
#define HEADS 12
#define DHEAD 64
#define HALF  64
#define SCALE 0.125f  /* 64^-0.5 */

// ---------------- scratch (device globals; no allocations allowed) ----------
__device__ float g_Q[(size_t)BATCH * HEADS * NTOK * DHEAD];
__device__ float g_K[(size_t)BATCH * HEADS * NTOK * DHEAD];
__device__ float g_V[(size_t)BATCH * HEADS * NTOK * DHEAD];
__device__ float g_O[(size_t)BATCH * NTOK * CDIM];

// ---------------- helpers ----------------------------------------------------
__device__ __forceinline__ uint32_t smem_u32(const void* p) {
    uint32_t a;
    asm("{ .reg .u64 t; cvta.to.shared.u64 t, %1; cvt.u32.u64 %0, t; }"
        : "=r"(a) : "l"(p));
    return a;
}
__device__ __forceinline__ void ldsm4(uint32_t* r, uint32_t addr) {
    asm volatile("ldmatrix.sync.aligned.m8n8.x4.shared.b16 {%0,%1,%2,%3}, [%4];"
                 : "=r"(r[0]), "=r"(r[1]), "=r"(r[2]), "=r"(r[3]) : "r"(addr));
}
__device__ __forceinline__ void mma16816(float* d, const uint32_t* a,
                                         const uint32_t* b) {
    asm volatile(
        "mma.sync.aligned.m16n8k16.row.col.f32.bf16.bf16.f32 "
        "{%0,%1,%2,%3}, {%4,%5,%6,%7}, {%8,%9}, {%0,%1,%2,%3};"
        : "+f"(d[0]), "+f"(d[1]), "+f"(d[2]), "+f"(d[3])
        : "r"(a[0]), "r"(a[1]), "r"(a[2]), "r"(a[3]), "r"(b[0]), "r"(b[1]));
}
__device__ __forceinline__ uint32_t bits2(__nv_bfloat162 v) {
    return *reinterpret_cast<uint32_t*>(&v);
}
// split float4 -> (hi bf16x2 pair, lo bf16x2 pair) as two uint2
__device__ __forceinline__ void split4(float4 v, uint2& hi, uint2& lo) {
    __nv_bfloat162 h01 = __floats2bfloat162_rn(v.x, v.y);
    __nv_bfloat162 h23 = __floats2bfloat162_rn(v.z, v.w);
    __nv_bfloat162 l01 = __floats2bfloat162_rn(v.x - __low2float(h01),
                                               v.y - __high2float(h01));
    __nv_bfloat162 l23 = __floats2bfloat162_rn(v.z - __low2float(h23),
                                               v.w - __high2float(h23));
    hi = make_uint2(bits2(h01), bits2(h23));
    lo = make_uint2(bits2(l01), bits2(l23));
}

// ---------------- bf16x3 mma.sync GEMM: C[M,Nc] = A[M,768] @ B[Nc,768]^T -----
#define BK 32
#define SSTR 40
#define ATILE_B (128 * SSTR * 2)
#define BUF_B   (4 * ATILE_B)
#define GSMEM_BYTES (2 * BUF_B)
#define NCHUNK (CDIM / BK)

template <int MODE>
__global__ void __launch_bounds__(256, 1) tcgemm(const float* __restrict__ A,
                                                 const float* __restrict__ Bw,
                                                 const float* __restrict__ bias,
                                                 float* __restrict__ Cout) {
    extern __shared__ __align__(128) char smem[];
    const int tid = threadIdx.x;
    const int wid = tid >> 5, lane = tid & 31;
    const int m0w = (wid >> 2) * 64;
    const int n0w = (wid & 3) * 32;
    const int rowBase = blockIdx.y * 128;
    const int colBase = blockIdx.x * 128;
    const float* Asrc = (MODE == 1) ? (const float*)g_O : A;
    const uint32_t sbase = smem_u32(smem);

    const int sr = tid >> 3;
    const int sc = (tid & 7) * 4;

    float4 aR[4], bR[4];
    auto ldgch = [&](int k0) {
#pragma unroll
        for (int u = 0; u < 4; u++) {
            int r = u * 32 + sr;
            aR[u] = *reinterpret_cast<const float4*>(
                Asrc + (size_t)(rowBase + r) * CDIM + k0 + sc);
            bR[u] = *reinterpret_cast<const float4*>(
                Bw + (size_t)(colBase + r) * CDIM + k0 + sc);
        }
    };

    float acc[4][4][4] = {};
    ldgch(0);

    for (int c = 0; c < NCHUNK; c++) {
        char* bufp = smem + (c & 1) * BUF_B;
        const uint32_t bufu = sbase + (c & 1) * BUF_B;

#pragma unroll
        for (int u = 0; u < 4; u++) {
            int r = u * 32 + sr;
            uint32_t off = (uint32_t)(r * SSTR + sc) * 2;
            uint2 hi, lo;
            split4(aR[u], hi, lo);
            *reinterpret_cast<uint2*>(bufp + off) = hi;
            *reinterpret_cast<uint2*>(bufp + ATILE_B + off) = lo;
            split4(bR[u], hi, lo);
            *reinterpret_cast<uint2*>(bufp + 2 * ATILE_B + off) = hi;
            *reinterpret_cast<uint2*>(bufp + 3 * ATILE_B + off) = lo;
        }
        __syncthreads();

        if (c + 1 < NCHUNK) ldgch((c + 1) * BK);

#pragma unroll
        for (int ks = 0; ks < 2; ks++) {
            const int k16 = ks * 16;
            uint32_t aHi[4][4], aLo[4][4], bHi[2][4], bLo[2][4];

            uint32_t aoff =
                bufu + (uint32_t)((m0w + (lane & 15)) * SSTR + k16 + (lane >> 4) * 8) * 2;
#pragma unroll
            for (int mi = 0; mi < 4; mi++) {
                ldsm4(aHi[mi], aoff + mi * (16 * SSTR * 2));
                ldsm4(aLo[mi], aoff + ATILE_B + mi * (16 * SSTR * 2));
            }
            {
                int g = lane >> 3, w8 = lane & 7;
                uint32_t boff = bufu + 2 * ATILE_B +
                                (uint32_t)((n0w + (g >> 1) * 8 + w8) * SSTR + k16 +
                                           (g & 1) * 8) * 2;
#pragma unroll
                for (int np = 0; np < 2; np++) {
                    ldsm4(bHi[np], boff + np * (16 * SSTR * 2));
                    ldsm4(bLo[np], boff + ATILE_B + np * (16 * SSTR * 2));
                }
            }
#pragma unroll
            for (int mi = 0; mi < 4; mi++)
#pragma unroll
                for (int ni = 0; ni < 4; ni++) {
                    const uint32_t* bh = &bHi[ni >> 1][(ni & 1) * 2];
                    const uint32_t* bl = &bLo[ni >> 1][(ni & 1) * 2];
                    mma16816(acc[mi][ni], aHi[mi], bh);
                    mma16816(acc[mi][ni], aHi[mi], bl);
                    mma16816(acc[mi][ni], aLo[mi], bh);
                }
        }
    }

#pragma unroll
    for (int mi = 0; mi < 4; mi++) {
        int m = rowBase + m0w + 16 * mi + (lane >> 2);
#pragma unroll
        for (int ni = 0; ni < 4; ni++) {
            int e = colBase + n0w + 8 * ni + (lane & 3) * 2;
            float2 v0 = make_float2(acc[mi][ni][0], acc[mi][ni][1]);
            float2 v1 = make_float2(acc[mi][ni][2], acc[mi][ni][3]);
            if (MODE == 0) {
                int tsel = e / CDIM;
                int rr = e - tsel * CDIM;
                int h = rr >> 6, d = rr & 63;
                float* dst = (tsel == 0) ? g_Q : ((tsel == 1) ? g_K : g_V);
                int bb = m >> 11, n = m & (NTOK - 1);
                size_t base = ((size_t)(bb * HEADS + h)) * NTOK;
                *reinterpret_cast<float2*>(&dst[(base + n) * DHEAD + d]) = v0;
                *reinterpret_cast<float2*>(&dst[(base + n + 8) * DHEAD + d]) = v1;
            } else {
                float2 bv = *reinterpret_cast<const float2*>(&bias[e]);
                v0.x += bv.x; v0.y += bv.y;
                v1.x += bv.x; v1.y += bv.y;
                *reinterpret_cast<float2*>(&Cout[(size_t)m * CDIM + e]) = v0;
                *reinterpret_cast<float2*>(&Cout[(size_t)(m + 8) * CDIM + e]) = v1;
            }
        }
    }
}

// ---------------- Sliding-window attention, bf16x3 mma.sync ------------------
// One CTA per (b*H+h, 64-query tile); 192 key slots (zero-padded at edges).
// smem (bytes):
//   sQh [64][72]  @ 0       sQl @ 9216
//   sKh [192][72] @ 18432   sKl @ 46080      (region reused for S then P)
//   S   [64][196] fp32 @ 18432
//   Ph  [64][200] @ 18432   Pl @ 44032
//   sVth[64][200] @ 73728   sVtl @ 99328     (V transposed: rows=d, cols=s)
#define KSLOTS 192
#define QSTR 72
#define KSTR 72
#define PSTR 200
#define VSTR 200
#define SSTRIDE 196
#define OFF_QH 0
#define OFF_QL 9216
#define OFF_KH 18432
#define OFF_KL 46080
#define OFF_S  18432
#define OFF_PH 18432
#define OFF_PL 44032
#define OFF_VTH 73728
#define OFF_VTL 99328
#define ATT_SMEM 124928

__global__ void __launch_bounds__(256) attn_mma() {
    extern __shared__ __align__(128) char sm[];
    const uint32_t sb = smem_u32(sm);
    const int tid = threadIdx.x;
    const int wid = tid >> 5, lane = tid & 31;
    const int q0 = blockIdx.x * 64;
    const int bh = blockIdx.y;
    const int kstart = q0 - HALF;

    const float* Qg = g_Q + (size_t)bh * NTOK * DHEAD;
    const float* Kg = g_K + (size_t)bh * NTOK * DHEAD;
    const float* Vg = g_V + (size_t)bh * NTOK * DHEAD;

    // ---- load + hi/lo split ----
    for (int idx = tid; idx < 64 * 16; idx += 256) {
        int q = idx >> 4, d4 = (idx & 15) << 2;
        float4 v = *reinterpret_cast<const float4*>(&Qg[(size_t)(q0 + q) * DHEAD + d4]);
        uint2 hi, lo;
        split4(v, hi, lo);
        uint32_t off = (uint32_t)(q * QSTR + d4) * 2;
        *reinterpret_cast<uint2*>(sm + OFF_QH + off) = hi;
        *reinterpret_cast<uint2*>(sm + OFF_QL + off) = lo;
    }
    for (int idx = tid; idx < KSLOTS * 16; idx += 256) {
        int s = idx >> 4, d4 = (idx & 15) << 2;
        int j = kstart + s;
        float4 kv = make_float4(0.f, 0.f, 0.f, 0.f);
        float4 vv = kv;
        if (j >= 0 && j < NTOK) {
            kv = *reinterpret_cast<const float4*>(&Kg[(size_t)j * DHEAD + d4]);
            vv = *reinterpret_cast<const float4*>(&Vg[(size_t)j * DHEAD + d4]);
        }
        uint2 hi, lo;
        split4(kv, hi, lo);
        uint32_t off = (uint32_t)(s * KSTR + d4) * 2;
        *reinterpret_cast<uint2*>(sm + OFF_KH + off) = hi;
        *reinterpret_cast<uint2*>(sm + OFF_KL + off) = lo;
        // V transposed scalar stores
        float vf[4] = {vv.x, vv.y, vv.z, vv.w};
#pragma unroll
        for (int i = 0; i < 4; i++) {
            __nv_bfloat16 h = __float2bfloat16_rn(vf[i]);
            __nv_bfloat16 l = __float2bfloat16_rn(vf[i] - __bfloat162float(h));
            ((__nv_bfloat16*)(sm + OFF_VTH))[(d4 + i) * VSTR + s] = h;
            ((__nv_bfloat16*)(sm + OFF_VTL))[(d4 + i) * VSTR + s] = l;
        }
    }
    __syncthreads();

    // ---- QK^T: warp grid 2x4 (m 2x32, n 4x48) ----
    const int wm = (wid >> 2) * 32;
    const int wn = (wid & 3) * 48;
    float sacc[2][6][4] = {};
    {
        const int g = lane >> 3, w8 = lane & 7;
#pragma unroll
        for (int ks = 0; ks < 4; ks++) {
            const int k16 = ks * 16;
            uint32_t qh[2][4], ql[2][4], kh[3][4], kl[3][4];
            uint32_t aoff = sb + OFF_QH +
                (uint32_t)((wm + (lane & 15)) * QSTR + k16 + (lane >> 4) * 8) * 2;
#pragma unroll
            for (int mi = 0; mi < 2; mi++) {
                ldsm4(qh[mi], aoff + mi * (16 * QSTR * 2));
                ldsm4(ql[mi], aoff + (OFF_QL - OFF_QH) + mi * (16 * QSTR * 2));
            }
            uint32_t boff = sb + OFF_KH +
                (uint32_t)((wn + (g >> 1) * 8 + w8) * KSTR + k16 + (g & 1) * 8) * 2;
#pragma unroll
            for (int np = 0; np < 3; np++) {
                ldsm4(kh[np], boff + np * (16 * KSTR * 2));
                ldsm4(kl[np], boff + (OFF_KL - OFF_KH) + np * (16 * KSTR * 2));
            }
#pragma unroll
            for (int mi = 0; mi < 2; mi++)
#pragma unroll
                for (int nt = 0; nt < 6; nt++) {
                    const uint32_t* bhh = &kh[nt >> 1][(nt & 1) * 2];
                    const uint32_t* bll = &kl[nt >> 1][(nt & 1) * 2];
                    mma16816(sacc[mi][nt], qh[mi], bhh);
                    mma16816(sacc[mi][nt], qh[mi], bll);
                    mma16816(sacc[mi][nt], ql[mi], bhh);
                }
        }
    }
    __syncthreads();  // all K reads done; region becomes S

    // ---- scale + mask, write S fp32 ----
    float* S = (float*)(sm + OFF_S);
#pragma unroll
    for (int mi = 0; mi < 2; mi++) {
        int qA = wm + 16 * mi + (lane >> 2);
#pragma unroll
        for (int nt = 0; nt < 6; nt++) {
            int s0 = wn + 8 * nt + (lane & 3) * 2;
#pragma unroll
            for (int half = 0; half < 2; half++) {
                int q = qA + half * 8;
#pragma unroll
                for (int e = 0; e < 2; e++) {
                    int s = s0 + e;
                    int kj = kstart + s;
                    int diff = q + HALF - s;
                    bool ok = (kj >= 0) & (kj < NTOK) & (diff >= -HALF) & (diff <= HALF);
                    S[q * SSTRIDE + s] =
                        ok ? sacc[mi][nt][half * 2 + e] * SCALE : -3.0e38f;
                }
            }
        }
    }
    __syncthreads();

    // ---- softmax: 4 threads/row, 48 slots each, values in registers ----
    {
        const int row = tid >> 2, part = tid & 3;
        const float* srow = S + row * SSTRIDE + part * 48;
        float vals[48];
#pragma unroll
        for (int i = 0; i < 12; i++) {
            float4 v = *reinterpret_cast<const float4*>(srow + 4 * i);
            vals[4 * i] = v.x; vals[4 * i + 1] = v.y;
            vals[4 * i + 2] = v.z; vals[4 * i + 3] = v.w;
        }
        float mx = -3.0e38f;
#pragma unroll
        for (int i = 0; i < 48; i++) mx = fmaxf(mx, vals[i]);
        mx = fmaxf(mx, __shfl_xor_sync(0xffffffff, mx, 1));
        mx = fmaxf(mx, __shfl_xor_sync(0xffffffff, mx, 2));
        float sum = 0.f;
#pragma unroll
        for (int i = 0; i < 48; i++) {
            vals[i] = __expf(vals[i] - mx);
            sum += vals[i];
        }
        sum += __shfl_xor_sync(0xffffffff, sum, 1);
        sum += __shfl_xor_sync(0xffffffff, sum, 2);
        float inv = __fdividef(1.f, sum);
        __syncthreads();  // all S reads complete; region becomes P
        uint32_t pbase = (uint32_t)(row * PSTR + part * 48) * 2;
#pragma unroll
        for (int i = 0; i < 24; i++) {
            float a = vals[2 * i] * inv, b = vals[2 * i + 1] * inv;
            __nv_bfloat162 h = __floats2bfloat162_rn(a, b);
            __nv_bfloat162 l = __floats2bfloat162_rn(a - __low2float(h),
                                                     b - __high2float(h));
            *reinterpret_cast<uint32_t*>(sm + OFF_PH + pbase + 4 * i) = bits2(h);
            *reinterpret_cast<uint32_t*>(sm + OFF_PL + pbase + 4 * i) = bits2(l);
        }
    }
    __syncthreads();

    // ---- PV: warp grid 2x4 (m 2x32, n(d) 4x16) ----
    const int wn2 = (wid & 3) * 16;
    float facc[2][2][4] = {};
    {
        const int g = lane >> 3, w8 = lane & 7;
#pragma unroll
        for (int ks = 0; ks < 12; ks++) {
            const int k16 = ks * 16;
            uint32_t ph[2][4], pl[2][4], vh[4], vl[4];
            uint32_t aoff = sb + OFF_PH +
                (uint32_t)((wm + (lane & 15)) * PSTR + k16 + (lane >> 4) * 8) * 2;
#pragma unroll
            for (int mi = 0; mi < 2; mi++) {
                ldsm4(ph[mi], aoff + mi * (16 * PSTR * 2));
                ldsm4(pl[mi], aoff + (OFF_PL - OFF_PH) + mi * (16 * PSTR * 2));
            }
            uint32_t boff = sb + OFF_VTH +
                (uint32_t)((wn2 + (g >> 1) * 8 + w8) * VSTR + k16 + (g & 1) * 8) * 2;
            ldsm4(vh, boff);
            ldsm4(vl, boff + (OFF_VTL - OFF_VTH));
#pragma unroll
            for (int mi = 0; mi < 2; mi++)
#pragma unroll
                for (int nt = 0; nt < 2; nt++) {
                    mma16816(facc[mi][nt], ph[mi], &vh[nt * 2]);
                    mma16816(facc[mi][nt], ph[mi], &vl[nt * 2]);
                    mma16816(facc[mi][nt], pl[mi], &vh[nt * 2]);
                }
        }
    }

    // ---- epilogue -> g_O [B,N,C] ----
    const int b = bh / HEADS, h = bh - b * HEADS;
#pragma unroll
    for (int mi = 0; mi < 2; mi++) {
        int n = q0 + wm + 16 * mi + (lane >> 2);
#pragma unroll
        for (int nt = 0; nt < 2; nt++) {
            int d = wn2 + 8 * nt + (lane & 3) * 2;
            float* p0 = &g_O[((size_t)b * NTOK + n) * CDIM + h * DHEAD + d];
            float* p1 = &g_O[((size_t)b * NTOK + n + 8) * CDIM + h * DHEAD + d];
            *reinterpret_cast<float2*>(p0) = make_float2(facc[mi][nt][0], facc[mi][nt][1]);
            *reinterpret_cast<float2*>(p1) = make_float2(facc[mi][nt][2], facc[mi][nt][3]);
        }
    }
}

// ---------------- launch ----------------------------------------------------
extern "C" void kernel_launch(void* const* d_in, const int* in_sizes, int n_in,
                              void* d_out, int out_size) {
    (void)in_sizes; (void)n_in; (void)out_size;
    const float* x      = (const float*)d_in[0];
    const float* w_qkv  = (const float*)d_in[1];
    const float* w_proj = (const float*)d_in[2];
    const float* b_proj = (const float*)d_in[3];
    float* out = (float*)d_out;

    cudaFuncSetAttribute(tcgemm<0>, cudaFuncAttributeMaxDynamicSharedMemorySize,
                         GSMEM_BYTES);
    cudaFuncSetAttribute(tcgemm<1>, cudaFuncAttributeMaxDynamicSharedMemorySize,
                         GSMEM_BYTES);
    cudaFuncSetAttribute(attn_mma, cudaFuncAttributeMaxDynamicSharedMemorySize,
                         ATT_SMEM);

    // 1) QKV projection (bf16x3 mma.sync) -> Q/K/V per-head buffers
    tcgemm<0><<<dim3(3 * CDIM / 128, BATCH * NTOK / 128), 256, GSMEM_BYTES>>>(
        x, w_qkv, nullptr, nullptr);

    // 2) Sliding-window attention (bf16x3 mma.sync) -> g_O ([B,N,C] layout)
    attn_mma<<<dim3(NTOK / 64, BATCH * HEADS), 256, ATT_SMEM>>>();

    // 3) Output projection + bias (bf16x3 mma.sync) -> d_out
    tcgemm<1><<<dim3(CDIM / 128, BATCH * NTOK / 128), 256, GSMEM_BYTES>>>(
        nullptr, w_proj, b_proj, out);
}